// round 13
// baseline (speedup 1.0000x reference)
#include <cuda_runtime.h>

#define NQ 16
#define BATCH 512
#define MAXT 8192
#define MAXG 384
#define MAXP (MAXT + MAXG * 31)
#define NWARP 16
#define S 4                       // samples per CTA
#define GRID (BATCH / S)

// ---------------------------------------------------------------------------
// Compile-time Pauli back-propagation term table (identical math to R6-R9,
// all passed at rel_err ~9e-6), padded into 32-term groups — all constexpr.
// ---------------------------------------------------------------------------
struct TermTab {
    unsigned e[MAXT];   // 2 bits/qubit: 0=absent 1=cos(phi) 2=-sin(phi)
    unsigned c[MAXT];   // 2 bits/qubit: 0=absent 1=cos(th)  2=sin(th)
    float    s[MAXT];   // +-1 Aaronson-Gottesman sign
    int      off[NQ + 1];
};

constexpr unsigned xevolve(unsigned x) {
    for (int g = 15; g >= 0; g--) { int t = (g + 1) & 15; x ^= ((x >> g) & 1u) << t; }
    return x;
}

constexpr TermTab make_terms() {
    TermTab tt{};
    int total = 0;
    for (int i = 0; i < NQ; i++) {
        tt.off[i] = total;
        const unsigned Sm = (i == 0) ? 0xFFFEu : ((1u << (i + 1)) - 1u);

        unsigned zz = Sm;                                  // z-evolution (a-indep)
        for (int g = 15; g >= 0; g--) { int t = (g + 1) & 15; zz ^= ((zz >> t) & 1u) << g; }

        unsigned basis[NQ] = {};
        int d = 0;
        for (int q = 0; q < NQ; q++)
            if ((Sm >> q) & 1) basis[d++] = 1u << q;

        for (int q = 0; q < NQ; q++) {                     // null-space elimination
            if ((zz >> q) & 1) continue;
            int piv = -1;
            unsigned dot[NQ] = {};
            for (int k = 0; k < d; k++) {
                dot[k] = (xevolve(basis[k]) >> q) & 1u;
                if (dot[k] && piv < 0) piv = k;
            }
            if (piv < 0) continue;
            for (int k = 0; k < d; k++)
                if (dot[k] && k != piv) basis[k] ^= basis[piv];
            basis[piv] = basis[d - 1];
            d--;
        }

        const int cnt = 1 << d;
        for (int j = 0; j < cnt; j++) {
            unsigned a = 0;
            for (int k = 0; k < d; k++)
                if ((j >> k) & 1) a ^= basis[k];

            unsigned x = a, zv = Sm, sgn = 0;              // symplectic + A-G sign
            for (int g = 15; g >= 0; g--) {
                int c = g, t = (g + 1) & 15;
                unsigned xc = (x >> c) & 1u, zt = (zv >> t) & 1u;
                unsigned xt = (x >> t) & 1u, zc = (zv >> c) & 1u;
                sgn ^= xc & zt & (xt ^ zc ^ 1u);
                x  ^= xc << t;
                zv ^= zt << c;
            }

            unsigned es = 0, cs = 0;
            for (int q = 0; q < NQ; q++) {
                if ((zz >> q) & 1) es |= (((x >> q) & 1u) ? 2u : 1u) << (2 * q);
                if ((Sm >> q) & 1) cs |= (((a >> q) & 1u) ? 2u : 1u) << (2 * q);
            }
            tt.e[total] = es;
            tt.c[total] = cs;
            tt.s[total] = sgn ? -1.f : 1.f;
            total++;
        }
    }
    tt.off[NQ] = total;
    return tt;
}

struct __align__(16) PTerm { unsigned e, c; float s; int oid; };

struct Padded {
    PTerm t[MAXP];      // oid replicated into every padded term (pad: s=0)
    int   G;
};

constexpr Padded make_padded() {
    const TermTab tt = make_terms();
    Padded P{};
    int g = 0, pos = 0;
    for (int i = 0; i < NQ; i++) {
        for (int base = tt.off[i]; base < tt.off[i + 1]; base += 32) {
            for (int k = 0; k < 32; k++) {
                int idx = base + k;
                if (idx < tt.off[i + 1]) {
                    P.t[pos].e = tt.e[idx];
                    P.t[pos].c = tt.c[idx];
                    P.t[pos].s = tt.s[idx];
                } else {
                    P.t[pos].e = 0; P.t[pos].c = 0; P.t[pos].s = 0.f;  // pad -> 0
                }
                P.t[pos].oid = i;
                pos++;
            }
            g++;
        }
    }
    P.G = g;
    return P;
}

constexpr Padded PP = make_padded();
constexpr int G = PP.G;
constexpr int MAXIT = (G + NWARP - 1) / NWARP;
static_assert(make_terms().off[NQ] <= MAXT, "term overflow");
static_assert(G <= MAXG, "group overflow");

__device__ const Padded g_pp = PP;

// ---------------------------------------------------------------------------
// One CTA (512 thr, 16 warps) per 4 samples -> grid 128, one wave.
// Entry: preload <=MAXIT PTerms per thread (cold LDG overlaps prologue);
// fused one-sync prologue (512 threads == 512 E entries, float2 gmem reads);
// branch-free term loop keeping v[it][smp] in registers; ALL shuffle
// reductions deferred past the loop and pipelined together; lane 0 scatters
// into part[warp][smp][oid]; final 64-thread sum.
// ---------------------------------------------------------------------------
__global__ __launch_bounds__(512) void eval_kernel(
    const float* __restrict__ zin,
    const float* __restrict__ params,
    const float* __restrict__ w,
    float* __restrict__ out)
{
    __shared__ float E[S][8][16], W[8][16];
    __shared__ float part[NWARP][S][16];

    const int b0 = blockIdx.x * S;
    const int tid = threadIdx.x;
    const int lane = tid & 31;
    const int wp = tid >> 5;

    // ---- preload term data first: cold LDGs overlap everything below ----
    PTerm tm[MAXIT];
#pragma unroll
    for (int it = 0; it < MAXIT; it++) {
        int g = wp + it * NWARP;
        if (g < G) tm[it] = g_pp.t[g * 32 + lane];
        else       { tm[it].e = 0; tm[it].c = 0; tm[it].s = 0.f; tm[it].oid = 0; }
    }

    // ---- fused prologue: 512 threads == 512 E entries (float2 loads) ----
    {
        const int smp = tid >> 7, r = tid & 127;
        const int p = r >> 4, k = r & 15;
        const int s0 = k & 3, s1 = k >> 2;
        const float2 zz = *(const float2*)(zin + (b0 + smp) * NQ + 2 * p);
        const float2 pp = *(const float2*)(params + 2 * p);
        const float2 ww = *(const float2*)(w + 2 * p);
        float sn0, cs0, sn1, cs1;
        __sincosf(zz.x + pp.x + ww.x, &sn0, &cs0);
        __sincosf(zz.y + pp.y + ww.y, &sn1, &cs1);
        float f0 = (s0 == 0) ? 1.f : ((s0 == 1) ? cs0 : -sn0);   // <Z>=cos, <Y>=-sin
        float f1 = (s1 == 0) ? 1.f : ((s1 == 1) ? cs1 : -sn1);
        E[smp][p][k] = f0 * f1;
    }
    if (tid < 128) {                                 // W pair table (theta)
        const int p = tid >> 4, k = tid & 15;
        const int s0 = k & 3, s1 = k >> 2;
        const float2 th = *(const float2*)(w + NQ + 2 * p);
        float sn0, cs0, sn1, cs1;
        __sincosf(th.x, &sn0, &cs0);
        __sincosf(th.y, &sn1, &cs1);
        float f0 = (s0 == 0) ? 1.f : ((s0 == 1) ? cs0 : sn0);
        float f1 = (s1 == 0) ? 1.f : ((s1 == 1) ? cs1 : sn1);
        W[p][k] = f0 * f1;
    }
#pragma unroll
    for (int k = tid; k < NWARP * S * 16; k += 512)  // zero partials
        ((float*)part)[k] = 0.f;
    __syncthreads();

    // ---- branch-free term loop: pad iterations contribute exactly 0 ----
    float v[MAXIT][S];
#pragma unroll
    for (int it = 0; it < MAXIT; it++) {
        const unsigned e = tm[it].e, c = tm[it].c;

        float w1 = tm[it].s, w2 = 1.f;               // sample-independent product
        w1 *= W[0][ c        & 15];  w2 *= W[1][(c >>  4) & 15];
        w1 *= W[2][(c >>  8) & 15];  w2 *= W[3][(c >> 12) & 15];
        w1 *= W[4][(c >> 16) & 15];  w2 *= W[5][(c >> 20) & 15];
        w1 *= W[6][(c >> 24) & 15];  w2 *= W[7][(c >> 28) & 15];
        const float wprod = w1 * w2;

#pragma unroll
        for (int smp = 0; smp < S; smp++) {
            float p1 = wprod, p2 = 1.f;
            p1 *= E[smp][0][ e        & 15];  p2 *= E[smp][1][(e >>  4) & 15];
            p1 *= E[smp][2][(e >>  8) & 15];  p2 *= E[smp][3][(e >> 12) & 15];
            p1 *= E[smp][4][(e >> 16) & 15];  p2 *= E[smp][5][(e >> 20) & 15];
            p1 *= E[smp][6][(e >> 24) & 15];  p2 *= E[smp][7][(e >> 28) & 15];
            v[it][smp] = p1 * p2;
        }
    }

    // ---- deferred, fully pipelined butterfly reduces (MAXIT*S chains) ----
#pragma unroll
    for (int o = 16; o; o >>= 1)
#pragma unroll
        for (int it = 0; it < MAXIT; it++)
#pragma unroll
            for (int smp = 0; smp < S; smp++)
                v[it][smp] += __shfl_xor_sync(0xffffffffu, v[it][smp], o);

    if (lane == 0) {
#pragma unroll
        for (int it = 0; it < MAXIT; it++) {
            const int oid = tm[it].oid;              // pad iters: oid 0, v == 0
#pragma unroll
            for (int smp = 0; smp < S; smp++)
                part[wp][smp][oid] += v[it][smp];
        }
    }
    __syncthreads();

    if (tid < S * NQ) {
        const int smp = tid >> 4, q = tid & 15;
        float sum = 0.f;
#pragma unroll
        for (int k = 0; k < NWARP; k++) sum += part[k][smp][q];
        out[(b0 + smp) * NQ + q] = sum;
    }
}

extern "C" void kernel_launch(void* const* d_in, const int* in_sizes, int n_in,
                              void* d_out, int out_size) {
    const float* z      = (const float*)d_in[0];   // [512,16]
    const float* params = (const float*)d_in[1];   // [16]
    const float* w      = (const float*)d_in[2];   // ent_weights [2,16]
    float* out = (float*)d_out;                    // [512,16] float32

    eval_kernel<<<GRID, 512>>>(z, params, w, out);
}

// round 14
// speedup vs baseline: 1.0382x; 1.0382x over previous
#include <cuda_runtime.h>

#define NQ 16
#define BATCH 512
#define MAXT 8192
#define MAXG 384
#define MAXP (MAXT + MAXG * 31)
#define NWARP 16
#define S 4                       // samples per CTA
#define GRID (BATCH / S)

// ---------------------------------------------------------------------------
// Compile-time Pauli back-propagation term table (identical math to R6-R10,
// all passed at rel_err ~9e-6), padded into 32-term groups — all constexpr.
// ---------------------------------------------------------------------------
struct TermTab {
    unsigned e[MAXT];   // 2 bits/qubit: 0=absent 1=cos(phi) 2=-sin(phi)
    unsigned c[MAXT];   // 2 bits/qubit: 0=absent 1=cos(th)  2=sin(th)
    float    s[MAXT];   // +-1 Aaronson-Gottesman sign
    int      off[NQ + 1];
};

constexpr unsigned xevolve(unsigned x) {
    for (int g = 15; g >= 0; g--) { int t = (g + 1) & 15; x ^= ((x >> g) & 1u) << t; }
    return x;
}

constexpr TermTab make_terms() {
    TermTab tt{};
    int total = 0;
    for (int i = 0; i < NQ; i++) {
        tt.off[i] = total;
        const unsigned Sm = (i == 0) ? 0xFFFEu : ((1u << (i + 1)) - 1u);

        unsigned zz = Sm;                                  // z-evolution (a-indep)
        for (int g = 15; g >= 0; g--) { int t = (g + 1) & 15; zz ^= ((zz >> t) & 1u) << g; }

        unsigned basis[NQ] = {};
        int d = 0;
        for (int q = 0; q < NQ; q++)
            if ((Sm >> q) & 1) basis[d++] = 1u << q;

        for (int q = 0; q < NQ; q++) {                     // null-space elimination
            if ((zz >> q) & 1) continue;
            int piv = -1;
            unsigned dot[NQ] = {};
            for (int k = 0; k < d; k++) {
                dot[k] = (xevolve(basis[k]) >> q) & 1u;
                if (dot[k] && piv < 0) piv = k;
            }
            if (piv < 0) continue;
            for (int k = 0; k < d; k++)
                if (dot[k] && k != piv) basis[k] ^= basis[piv];
            basis[piv] = basis[d - 1];
            d--;
        }

        const int cnt = 1 << d;
        for (int j = 0; j < cnt; j++) {
            unsigned a = 0;
            for (int k = 0; k < d; k++)
                if ((j >> k) & 1) a ^= basis[k];

            unsigned x = a, zv = Sm, sgn = 0;              // symplectic + A-G sign
            for (int g = 15; g >= 0; g--) {
                int c = g, t = (g + 1) & 15;
                unsigned xc = (x >> c) & 1u, zt = (zv >> t) & 1u;
                unsigned xt = (x >> t) & 1u, zc = (zv >> c) & 1u;
                sgn ^= xc & zt & (xt ^ zc ^ 1u);
                x  ^= xc << t;
                zv ^= zt << c;
            }

            unsigned es = 0, cs = 0;
            for (int q = 0; q < NQ; q++) {
                if ((zz >> q) & 1) es |= (((x >> q) & 1u) ? 2u : 1u) << (2 * q);
                if ((Sm >> q) & 1) cs |= (((a >> q) & 1u) ? 2u : 1u) << (2 * q);
            }
            tt.e[total] = es;
            tt.c[total] = cs;
            tt.s[total] = sgn ? -1.f : 1.f;
            total++;
        }
    }
    tt.off[NQ] = total;
    return tt;
}

struct __align__(16) PTerm { unsigned e, c; float s; int oid; };

struct Padded {
    PTerm t[MAXP];      // oid replicated into every padded term (pad: s=0)
    int   G;
};

constexpr Padded make_padded() {
    const TermTab tt = make_terms();
    Padded P{};
    int g = 0, pos = 0;
    for (int i = 0; i < NQ; i++) {
        for (int base = tt.off[i]; base < tt.off[i + 1]; base += 32) {
            for (int k = 0; k < 32; k++) {
                int idx = base + k;
                if (idx < tt.off[i + 1]) {
                    P.t[pos].e = tt.e[idx];
                    P.t[pos].c = tt.c[idx];
                    P.t[pos].s = tt.s[idx];
                } else {
                    P.t[pos].e = 0; P.t[pos].c = 0; P.t[pos].s = 0.f;  // pad -> 0
                }
                P.t[pos].oid = i;
                pos++;
            }
            g++;
        }
    }
    P.G = g;
    return P;
}

constexpr Padded PP = make_padded();
constexpr int G = PP.G;
constexpr int MAXIT = (G + NWARP - 1) / NWARP;
static_assert(make_terms().off[NQ] <= MAXT, "term overflow");
static_assert(G <= MAXG, "group overflow");

__device__ const Padded g_pp = PP;

// ---------------------------------------------------------------------------
// One CTA (512 thr, 16 warps) per 4 samples -> grid 128, one wave.
// R9 structure (best measured): preload <=MAXIT PTerms (cold LDG overlaps
// prologue); fused one-sync prologue (512 threads == 512 E entries, float2
// loads); branch-free term loop with IN-LOOP shfl reduce (keeps live state
// inside the 32-reg budget — the R10 deferred variant spilled); lane 0
// scatters into part[warp][smp][oid]; final 64-thread sum.
// ---------------------------------------------------------------------------
__global__ __launch_bounds__(512) void eval_kernel(
    const float* __restrict__ zin,
    const float* __restrict__ params,
    const float* __restrict__ w,
    float* __restrict__ out)
{
    __shared__ float E[S][8][16], W[8][16];
    __shared__ float part[NWARP][S][16];

    const int b0 = blockIdx.x * S;
    const int tid = threadIdx.x;
    const int lane = tid & 31;
    const int wp = tid >> 5;

    // ---- preload term data first: cold LDGs overlap everything below ----
    PTerm tm[MAXIT];
#pragma unroll
    for (int it = 0; it < MAXIT; it++) {
        int g = wp + it * NWARP;
        if (g < G) tm[it] = g_pp.t[g * 32 + lane];
        else       { tm[it].e = 0; tm[it].c = 0; tm[it].s = 0.f; tm[it].oid = 0; }
    }

    // ---- fused prologue: 512 threads == 512 E entries (float2 loads) ----
    {
        const int smp = tid >> 7, r = tid & 127;
        const int p = r >> 4, k = r & 15;
        const int s0 = k & 3, s1 = k >> 2;
        const float2 zz = *(const float2*)(zin + (b0 + smp) * NQ + 2 * p);
        const float2 pp = *(const float2*)(params + 2 * p);
        const float2 ww = *(const float2*)(w + 2 * p);
        float sn0, cs0, sn1, cs1;
        __sincosf(zz.x + pp.x + ww.x, &sn0, &cs0);
        __sincosf(zz.y + pp.y + ww.y, &sn1, &cs1);
        float f0 = (s0 == 0) ? 1.f : ((s0 == 1) ? cs0 : -sn0);   // <Z>=cos, <Y>=-sin
        float f1 = (s1 == 0) ? 1.f : ((s1 == 1) ? cs1 : -sn1);
        E[smp][p][k] = f0 * f1;
    }
    if (tid < 128) {                                 // W pair table (theta)
        const int p = tid >> 4, k = tid & 15;
        const int s0 = k & 3, s1 = k >> 2;
        const float2 th = *(const float2*)(w + NQ + 2 * p);
        float sn0, cs0, sn1, cs1;
        __sincosf(th.x, &sn0, &cs0);
        __sincosf(th.y, &sn1, &cs1);
        float f0 = (s0 == 0) ? 1.f : ((s0 == 1) ? cs0 : sn0);
        float f1 = (s1 == 0) ? 1.f : ((s1 == 1) ? cs1 : sn1);
        W[p][k] = f0 * f1;
    }
#pragma unroll
    for (int k = tid; k < NWARP * S * 16; k += 512)  // zero partials
        ((float*)part)[k] = 0.f;
    __syncthreads();

    // ---- branch-free term loop, in-loop reduce (fits 32-reg budget) ----
#pragma unroll
    for (int it = 0; it < MAXIT; it++) {
        const unsigned e = tm[it].e, c = tm[it].c;

        float w1 = tm[it].s, w2 = 1.f;               // sample-independent product
        w1 *= W[0][ c        & 15];  w2 *= W[1][(c >>  4) & 15];
        w1 *= W[2][(c >>  8) & 15];  w2 *= W[3][(c >> 12) & 15];
        w1 *= W[4][(c >> 16) & 15];  w2 *= W[5][(c >> 20) & 15];
        w1 *= W[6][(c >> 24) & 15];  w2 *= W[7][(c >> 28) & 15];
        const float wprod = w1 * w2;

        float v[S];
#pragma unroll
        for (int smp = 0; smp < S; smp++) {
            float p1 = wprod, p2 = 1.f;
            p1 *= E[smp][0][ e        & 15];  p2 *= E[smp][1][(e >>  4) & 15];
            p1 *= E[smp][2][(e >>  8) & 15];  p2 *= E[smp][3][(e >> 12) & 15];
            p1 *= E[smp][4][(e >> 16) & 15];  p2 *= E[smp][5][(e >> 20) & 15];
            p1 *= E[smp][6][(e >> 24) & 15];  p2 *= E[smp][7][(e >> 28) & 15];
            v[smp] = p1 * p2;
        }
#pragma unroll
        for (int o = 16; o; o >>= 1) {               // 4 independent, pipelined
#pragma unroll
            for (int smp = 0; smp < S; smp++)
                v[smp] += __shfl_down_sync(0xffffffffu, v[smp], o);
        }
        if (lane == 0) {
            const int oid = tm[it].oid;              // pad iters: oid 0, v == 0
#pragma unroll
            for (int smp = 0; smp < S; smp++)
                part[wp][smp][oid] += v[smp];
        }
    }
    __syncthreads();

    if (tid < S * NQ) {
        const int smp = tid >> 4, q = tid & 15;
        float sum = 0.f;
#pragma unroll
        for (int k = 0; k < NWARP; k++) sum += part[k][smp][q];
        out[(b0 + smp) * NQ + q] = sum;
    }
}

extern "C" void kernel_launch(void* const* d_in, const int* in_sizes, int n_in,
                              void* d_out, int out_size) {
    const float* z      = (const float*)d_in[0];   // [512,16]
    const float* params = (const float*)d_in[1];   // [16]
    const float* w      = (const float*)d_in[2];   // ent_weights [2,16]
    float* out = (float*)d_out;                    // [512,16] float32

    eval_kernel<<<GRID, 512>>>(z, params, w, out);
}